// round 1
// baseline (speedup 1.0000x reference)
#include <cuda_runtime.h>

// Problem constants
#define SQ   1024          // seq len
#define DH   64            // head dim
#define NBH  32            // B*H = 2*16

// Scratch (device globals; no allocation allowed)
__device__ float g_partial[8 * NBH * SQ];   // [kblk][bh*SQ + row]
__device__ float g_rinv[NBH * SQ];          // 1 / rowsum

// ---------------------------------------------------------------------------
// Kernel 1: E = exp(QK^T/8 + ia_type + ia_feat) with mask->0, stored into the
// attn region of d_out. Also writes deterministic per-(kblk,row) partial sums.
// Tile: 128q x 128k per block, 256 threads, 8x8 register blocking.
// ---------------------------------------------------------------------------
__global__ __launch_bounds__(256) void k_scores(
    const float* __restrict__ Q, const float* __restrict__ K,
    const float* __restrict__ iat, const float* __restrict__ iaf,
    const unsigned int* __restrict__ mask, float* __restrict__ E)
{
    const int kb = blockIdx.x;   // 0..7  k tile
    const int qb = blockIdx.y;   // 0..7  q tile
    const int bh = blockIdx.z;   // 0..31

    extern __shared__ float sm[];
    float* Qs = sm;                    // 128 x 68 (pad)
    float* Ks = sm + 128 * 68;         // 128 x 68
    float* Rs = sm + 2 * 128 * 68;     // 128 x 16 partial sums

    const int tid = threadIdx.x;
    const int tx = tid & 15;
    const int ty = tid >> 4;

    const float* Qg = Q + ((size_t)bh * SQ + (size_t)qb * 128) * DH;
    const float* Kg = K + ((size_t)bh * SQ + (size_t)kb * 128) * DH;

    // Load 128x64 tiles (2048 float4 each, 8 per thread)
#pragma unroll
    for (int it = 0; it < 8; it++) {
        int f4  = tid + it * 256;
        int row = f4 >> 4;            // 16 float4 per row
        int c4  = (f4 & 15) << 2;
        *(float4*)(Qs + row * 68 + c4) = *(const float4*)(Qg + row * DH + c4);
        *(float4*)(Ks + row * 68 + c4) = *(const float4*)(Kg + row * DH + c4);
    }
    __syncthreads();

    float acc[8][8];
#pragma unroll
    for (int i = 0; i < 8; i++)
#pragma unroll
        for (int j = 0; j < 8; j++) acc[i][j] = 0.f;

#pragma unroll 4
    for (int d = 0; d < DH; d++) {
        float qv[8], kv[8];
#pragma unroll
        for (int i = 0; i < 8; i++) qv[i] = Qs[(ty + i * 16) * 68 + d];
#pragma unroll
        for (int j = 0; j < 8; j++) kv[j] = Ks[(tx + j * 16) * 68 + d];
#pragma unroll
        for (int i = 0; i < 8; i++)
#pragma unroll
            for (int j = 0; j < 8; j++)
                acc[i][j] = fmaf(qv[i], kv[j], acc[i][j]);
    }
    __syncthreads();   // done with tiles; Rs region is separate but sync anyway

    // Epilogue: bias + mask + exp, write E, accumulate row partial sums
#pragma unroll
    for (int i = 0; i < 8; i++) {
        const int r = ty + i * 16;                         // local row
        const size_t gro = (((size_t)bh * SQ) + (size_t)qb * 128 + r) * SQ
                         + (size_t)kb * 128;
        float part = 0.f;
#pragma unroll
        for (int j = 0; j < 8; j++) {
            const int c = tx + j * 16;
            float e;
            if (mask[gro + c] != 0u) {
                e = 0.f;
            } else {
                float s = acc[i][j] * 0.125f + iat[gro + c] + iaf[gro + c];
                e = __expf(s);
            }
            part += e;
            E[gro + c] = e;
        }
        Rs[r * 16 + tx] = part;
    }
    __syncthreads();

    if (tid < 128) {
        float s = 0.f;
#pragma unroll
        for (int t = 0; t < 16; t++) s += Rs[tid * 16 + t];
        g_partial[(size_t)kb * (NBH * SQ) + (size_t)bh * SQ
                  + (size_t)qb * 128 + tid] = s;
    }
}

// ---------------------------------------------------------------------------
// Kernel 1b: reduce 8 partials -> 1/rowsum
// ---------------------------------------------------------------------------
__global__ __launch_bounds__(256) void k_rowsum()
{
    const int r = blockIdx.x * 256 + threadIdx.x;   // 0..32767
    float s = 0.f;
#pragma unroll
    for (int kb = 0; kb < 8; kb++) s += g_partial[kb * (NBH * SQ) + r];
    g_rinv[r] = 1.f / s;
}

// ---------------------------------------------------------------------------
// Kernel 2: normalize attn in place and compute context = rinv * (E @ V).
// Tile: 256q x 64d per block, k-loop in tiles of 128. 256 threads, 8x8 blocking.
// ---------------------------------------------------------------------------
__global__ __launch_bounds__(256) void k_pv(
    const float* __restrict__ V, float* __restrict__ attn,
    float* __restrict__ ctx)
{
    const int qb = blockIdx.x;   // 0..3
    const int bh = blockIdx.y;   // 0..31

    extern __shared__ float sm[];
    float* Es = sm;                                // 256 x 132 (pad)
    float* Vs = sm + 256 * 132;                    // 128 x 68
    float* Ri = sm + 256 * 132 + 128 * 68;         // 256

    const int tid = threadIdx.x;
    const int tx = tid & 7;      // d groups (8)
    const int ty = tid >> 3;     // row groups (32)

    Ri[tid] = g_rinv[(size_t)bh * SQ + (size_t)qb * 256 + tid];

    float acc[8][8];
#pragma unroll
    for (int i = 0; i < 8; i++)
#pragma unroll
        for (int j = 0; j < 8; j++) acc[i][j] = 0.f;

    for (int kt = 0; kt < 8; kt++) {
        __syncthreads();
        const size_t ebase = (((size_t)bh * SQ) + (size_t)qb * 256) * SQ
                           + (size_t)kt * 128;
        // Load E tile 256x128 (8192 float4, 32 per thread)
#pragma unroll
        for (int it = 0; it < 32; it++) {
            int f4  = tid + it * 256;
            int row = f4 >> 5;           // 32 float4 per row
            int c4  = (f4 & 31) << 2;
            *(float4*)(Es + row * 132 + c4) =
                *(const float4*)(attn + ebase + (size_t)row * SQ + c4);
        }
        // Load V tile 128x64 (2048 float4, 8 per thread)
        const float* Vg = V + ((size_t)bh * SQ + (size_t)kt * 128) * DH;
#pragma unroll
        for (int it = 0; it < 8; it++) {
            int f4  = tid + it * 256;
            int row = f4 >> 4;
            int c4  = (f4 & 15) << 2;
            *(float4*)(Vs + row * 68 + c4) = *(const float4*)(Vg + row * DH + c4);
        }
        __syncthreads();

        // Write normalized attn back (each (q,k) touched exactly once)
#pragma unroll
        for (int it = 0; it < 32; it++) {
            int f4  = tid + it * 256;
            int row = f4 >> 5;
            int c4  = (f4 & 31) << 2;
            float4 v = *(const float4*)(Es + row * 132 + c4);
            float rv = Ri[row];
            v.x *= rv; v.y *= rv; v.z *= rv; v.w *= rv;
            *(float4*)(attn + ebase + (size_t)row * SQ + c4) = v;
        }

        // GEMM: acc += E_tile @ V_tile
#pragma unroll 4
        for (int k = 0; k < 128; k++) {
            float ev[8], vv[8];
#pragma unroll
            for (int i = 0; i < 8; i++) ev[i] = Es[(ty + i * 32) * 132 + k];
#pragma unroll
            for (int j = 0; j < 8; j++) vv[j] = Vs[k * 68 + tx + j * 8];
#pragma unroll
            for (int i = 0; i < 8; i++)
#pragma unroll
                for (int j = 0; j < 8; j++)
                    acc[i][j] = fmaf(ev[i], vv[j], acc[i][j]);
        }
    }

    // Epilogue: scale by rinv, write context
#pragma unroll
    for (int i = 0; i < 8; i++) {
        const int r = ty + i * 32;
        const float rv = Ri[r];
        const size_t ob = (((size_t)bh * SQ) + (size_t)qb * 256 + r) * DH;
#pragma unroll
        for (int j = 0; j < 8; j++)
            ctx[ob + tx + j * 8] = acc[i][j] * rv;
    }
}

// ---------------------------------------------------------------------------
extern "C" void kernel_launch(void* const* d_in, const int* in_sizes, int n_in,
                              void* d_out, int out_size)
{
    const float*        Q    = (const float*)d_in[0];
    const float*        K    = (const float*)d_in[1];
    const float*        V    = (const float*)d_in[2];
    // d_in[3] = attn_mask (unused by reference math)
    const unsigned int* mask = (const unsigned int*)d_in[4];  // attn_mask_if
    const float*        iat  = (const float*)d_in[5];         // ia_type
    const float*        iaf  = (const float*)d_in[6];         // ia_feat
    // d_in[7] = distance_matrix (unused)

    float* ctx  = (float*)d_out;                       // [32, 1024, 64]
    float* attn = ctx + (size_t)NBH * SQ * DH;         // [32, 1024, 1024]

    const int smem1 = (2 * 128 * 68 + 128 * 16) * 4;           // 77824 B
    const int smem2 = (256 * 132 + 128 * 68 + 256) * 4;        // 171008 B
    cudaFuncSetAttribute(k_scores, cudaFuncAttributeMaxDynamicSharedMemorySize, smem1);
    cudaFuncSetAttribute(k_pv,     cudaFuncAttributeMaxDynamicSharedMemorySize, smem2);

    dim3 g1(8, 8, NBH);
    k_scores<<<g1, 256, smem1>>>(Q, K, iat, iaf, mask, attn);

    k_rowsum<<<(NBH * SQ) / 256, 256>>>();

    dim3 g2(4, NBH);
    k_pv<<<g2, 256, smem2>>>(V, attn, ctx);
}

// round 3
// speedup vs baseline: 1.2044x; 1.2044x over previous
#include <cuda_runtime.h>

#define SQ   1024
#define DH   64
#define NBH  32

__device__ float g_partial[8 * NBH * SQ];   // [kblk][bh*SQ + row]
__device__ float g_rinv[NBH * SQ];

// ---------------------------------------------------------------------------
// Kernel 1: E = exp(QK^T/8 + ia_type + ia_feat), mask->0, into attn region.
// 128q x 128k tile, 256 threads, 8x8 register GEMM, acc staged through smem,
// fully coalesced float4 epilogue with warp-shuffle row sums.
// ---------------------------------------------------------------------------
__global__ __launch_bounds__(256) void k_scores(
    const float* __restrict__ Q, const float* __restrict__ K,
    const float* __restrict__ iat, const float* __restrict__ iaf,
    const unsigned int* __restrict__ mask, float* __restrict__ E)
{
    const int kb = blockIdx.x;
    const int qb = blockIdx.y;
    const int bh = blockIdx.z;

    extern __shared__ float sm[];
    float* Qs = sm;                    // 128 x 68
    float* Ks = sm + 128 * 68;         // 128 x 68

    const int tid = threadIdx.x;
    const int tx = tid & 15;
    const int ty = tid >> 4;
    const int lane = tid & 31;
    const int w = tid >> 5;

    const float* Qg = Q + ((size_t)bh * SQ + (size_t)qb * 128) * DH;
    const float* Kg = K + ((size_t)bh * SQ + (size_t)kb * 128) * DH;

#pragma unroll
    for (int it = 0; it < 8; it++) {
        int f4  = tid + it * 256;
        int row = f4 >> 4;
        int c4  = (f4 & 15) << 2;
        *(float4*)(Qs + row * 68 + c4) = *(const float4*)(Qg + row * DH + c4);
        *(float4*)(Ks + row * 68 + c4) = *(const float4*)(Kg + row * DH + c4);
    }
    __syncthreads();

    float acc[8][8];
#pragma unroll
    for (int i = 0; i < 8; i++)
#pragma unroll
        for (int j = 0; j < 8; j++) acc[i][j] = 0.f;

#pragma unroll 4
    for (int d = 0; d < DH; d++) {
        float qv[8], kv[8];
#pragma unroll
        for (int i = 0; i < 8; i++) qv[i] = Qs[(ty + i * 16) * 68 + d];
#pragma unroll
        for (int j = 0; j < 8; j++) kv[j] = Ks[(tx + j * 16) * 68 + d];
#pragma unroll
        for (int i = 0; i < 8; i++)
#pragma unroll
            for (int j = 0; j < 8; j++)
                acc[i][j] = fmaf(qv[i], kv[j], acc[i][j]);
    }
    __syncthreads();

    // Stage accumulators through smem (reuse Qs/Ks region).
    // Row stride 132 floats: divisible by 4 so float4 reads stay 16B-aligned.
    float* Ss = sm;                    // 128 x 132 = 67584 B (fits in 69632)
#pragma unroll
    for (int i = 0; i < 8; i++)
#pragma unroll
        for (int j = 0; j < 8; j++)
            Ss[(ty + i * 16) * 132 + tx + j * 16] = acc[i][j];
    __syncthreads();

    // Coalesced epilogue: one warp = one full row per iteration
    const size_t base = (((size_t)bh * SQ) + (size_t)qb * 128) * SQ
                      + (size_t)kb * 128;
#pragma unroll 4
    for (int it = 0; it < 16; it++) {
        const int row = it * 8 + w;
        const int c   = lane << 2;
        const size_t g = base + (size_t)row * SQ + c;
        float4 a = *(const float4*)(iat + g);
        float4 b = *(const float4*)(iaf + g);
        uint4  m = *(const uint4*)(mask + g);
        float4 sv = *(const float4*)(Ss + row * 132 + c);
        float4 e;
        e.x = m.x ? 0.f : __expf(fmaf(sv.x, 0.125f, a.x + b.x));
        e.y = m.y ? 0.f : __expf(fmaf(sv.y, 0.125f, a.y + b.y));
        e.z = m.z ? 0.f : __expf(fmaf(sv.z, 0.125f, a.z + b.z));
        e.w = m.w ? 0.f : __expf(fmaf(sv.w, 0.125f, a.w + b.w));
        *(float4*)(E + g) = e;

        float part = (e.x + e.y) + (e.z + e.w);
#pragma unroll
        for (int o = 16; o > 0; o >>= 1)
            part += __shfl_xor_sync(0xffffffffu, part, o);
        if (lane == 0)
            g_partial[(size_t)kb * (NBH * SQ) + (size_t)bh * SQ
                      + (size_t)qb * 128 + row] = part;
    }
}

// ---------------------------------------------------------------------------
__global__ __launch_bounds__(256) void k_rowsum()
{
    const int r = blockIdx.x * 256 + threadIdx.x;
    float s = 0.f;
#pragma unroll
    for (int kb = 0; kb < 8; kb++) s += g_partial[kb * (NBH * SQ) + r];
    g_rinv[r] = 1.f / s;
}

// ---------------------------------------------------------------------------
// Kernel 2: normalize attn in place + context = rinv * (E @ V).
// 128q x 64d tile, k-tiles of 128, 256 threads, 8x4 register blocking.
// smem ~103KB -> 2 blocks/SM; 256 blocks = one wave.
// ---------------------------------------------------------------------------
__global__ __launch_bounds__(256) void k_pv(
    const float* __restrict__ V, float* __restrict__ attn,
    float* __restrict__ ctx)
{
    const int qb = blockIdx.x;   // 0..7
    const int bh = blockIdx.y;   // 0..31

    extern __shared__ float sm[];
    float* Es  = sm;                               // 128 x 132
    float* Vs  = sm + 128 * 132;                   // 128 x 68
    float* sRi = sm + 128 * 132 + 128 * 68;        // 128

    const int tid = threadIdx.x;
    const int tx = tid & 15;     // 16 col groups
    const int ty = tid >> 4;     // 16 row groups
    const int lane = tid & 31;
    const int w = tid >> 5;

    if (tid < 128)
        sRi[tid] = g_rinv[(size_t)bh * SQ + (size_t)qb * 128 + tid];
    __syncthreads();

    float acc[8][4];
#pragma unroll
    for (int i = 0; i < 8; i++)
#pragma unroll
        for (int j = 0; j < 4; j++) acc[i][j] = 0.f;

    for (int kt = 0; kt < 8; kt++) {
        __syncthreads();
        const size_t ebase = (((size_t)bh * SQ) + (size_t)qb * 128) * SQ
                           + (size_t)kt * 128;
        // E tile 128x128: coalesced, one warp = one row per it.
        // Also write back the normalized attn in the same pass.
#pragma unroll 4
        for (int it = 0; it < 16; it++) {
            const int row = it * 8 + w;
            const int c   = lane << 2;
            const size_t g = ebase + (size_t)row * SQ + c;
            float4 v = *(const float4*)(attn + g);
            *(float4*)(Es + row * 132 + c) = v;
            const float rv = sRi[row];
            v.x *= rv; v.y *= rv; v.z *= rv; v.w *= rv;
            *(float4*)(attn + g) = v;
        }
        // V tile 128x64
        const float* Vg = V + ((size_t)bh * SQ + (size_t)kt * 128) * DH;
#pragma unroll
        for (int it = 0; it < 8; it++) {
            int f4  = tid + it * 256;
            int row = f4 >> 4;
            int c4  = (f4 & 15) << 2;
            *(float4*)(Vs + row * 68 + c4) = *(const float4*)(Vg + row * DH + c4);
        }
        __syncthreads();

#pragma unroll 4
        for (int k = 0; k < 128; k++) {
            float ev[8], vv[4];
#pragma unroll
            for (int i = 0; i < 8; i++) ev[i] = Es[(ty + i * 16) * 132 + k];
#pragma unroll
            for (int j = 0; j < 4; j++) vv[j] = Vs[k * 68 + tx + j * 16];
#pragma unroll
            for (int i = 0; i < 8; i++)
#pragma unroll
                for (int j = 0; j < 4; j++)
                    acc[i][j] = fmaf(ev[i], vv[j], acc[i][j]);
        }
    }

#pragma unroll
    for (int i = 0; i < 8; i++) {
        const int r = ty + i * 16;
        const float rv = sRi[r];
        const size_t ob = (((size_t)bh * SQ) + (size_t)qb * 128 + r) * DH;
#pragma unroll
        for (int j = 0; j < 4; j++)
            ctx[ob + tx + j * 16] = acc[i][j] * rv;
    }
}

// ---------------------------------------------------------------------------
extern "C" void kernel_launch(void* const* d_in, const int* in_sizes, int n_in,
                              void* d_out, int out_size)
{
    const float*        Q    = (const float*)d_in[0];
    const float*        K    = (const float*)d_in[1];
    const float*        V    = (const float*)d_in[2];
    const unsigned int* mask = (const unsigned int*)d_in[4];  // attn_mask_if
    const float*        iat  = (const float*)d_in[5];
    const float*        iaf  = (const float*)d_in[6];

    float* ctx  = (float*)d_out;
    float* attn = ctx + (size_t)NBH * SQ * DH;

    const int smem1 = 2 * 128 * 68 * 4;                         // 69632 B
    const int smem2 = (128 * 132 + 128 * 68 + 128) * 4;         // 102912 B
    cudaFuncSetAttribute(k_scores, cudaFuncAttributeMaxDynamicSharedMemorySize, smem1);
    cudaFuncSetAttribute(k_pv,     cudaFuncAttributeMaxDynamicSharedMemorySize, smem2);

    dim3 g1(8, 8, NBH);
    k_scores<<<g1, 256, smem1>>>(Q, K, iat, iaf, mask, attn);

    k_rowsum<<<(NBH * SQ) / 256, 256>>>();

    dim3 g2(8, NBH);
    k_pv<<<g2, 256, smem2>>>(V, attn, ctx);
}